// round 13
// baseline (speedup 1.0000x reference)
#include <cuda_runtime.h>
#include <cuda_fp16.h>
#include <math.h>
#include <stdint.h>

// Problem constants
#define MTOT 32768      // B*T
#define DDIM 512
#define NCHUNK 64       // 4096/64
#define CHUNK 64

// GEMM tiling (BM=64, 256 thr, 2 CTA/SM, 4-stage)
#define BM 64
#define BN 256
#define BK 32
#define KSTAGES 16      // 512/32

#define A_OFF 0
#define B_OFF 5120
#define STAGE 25600
#define NSTAGE 4
#define DYN_SMEM (NSTAGE * STAGE)

#define SCAN_SMEM (CHUNK * DDIM * 4)   // 131072 B

// ---------------- device scratch ----------------
__device__ __half g_W[DDIM * DDIM];            // W^T fp16  [e][k]
__device__ float g_P[2][MTOT];                  // per-N-half partial scores
__device__ float g_CD[8 * NCHUNK];              // per-chunk den sums
__device__ float g_CN[8 * NCHUNK * DDIM];       // per-chunk num sums
__device__ int   g_flag[8 * NCHUNK];            // lookback publish flags

// ---------------- PTX helpers ----------------
__device__ __forceinline__ uint32_t smem_u32(const void* p) {
    uint32_t a;
    asm("{ .reg .u64 t; cvta.to.shared.u64 t, %1; cvt.u32.u64 %0, t; }" : "=r"(a) : "l"(p));
    return a;
}
#define CP_ASYNC16(sa, ga) \
    asm volatile("cp.async.cg.shared.global [%0], [%1], 16;" :: "r"(sa), "l"(ga) : "memory")
#define CP_COMMIT() asm volatile("cp.async.commit_group;" ::: "memory")
#define CP_WAIT0()  asm volatile("cp.async.wait_group 0;" ::: "memory")
#define CP_WAIT1()  asm volatile("cp.async.wait_group 1;" ::: "memory")
#define CP_WAIT2()  asm volatile("cp.async.wait_group 2;" ::: "memory")

#define LDM_X4(r, addr) \
    asm volatile("ldmatrix.sync.aligned.m8n8.x4.shared.b16 {%0,%1,%2,%3}, [%4];" \
        : "=r"((r)[0]), "=r"((r)[1]), "=r"((r)[2]), "=r"((r)[3]) : "r"(addr))
#define LDM_X2(r, addr) \
    asm volatile("ldmatrix.sync.aligned.m8n8.x2.shared.b16 {%0,%1}, [%2];" \
        : "=r"((r)[0]), "=r"((r)[1]) : "r"(addr))

#define MMA_F16(d, a, b) \
    asm volatile("mma.sync.aligned.m16n8k16.row.col.f32.f16.f16.f32 " \
        "{%0,%1,%2,%3}, {%4,%5,%6,%7}, {%8,%9}, {%0,%1,%2,%3};" \
        : "+f"((d)[0]), "+f"((d)[1]), "+f"((d)[2]), "+f"((d)[3]) \
        : "r"((a)[0]), "r"((a)[1]), "r"((a)[2]), "r"((a)[3]), "r"((b)[0]), "r"((b)[1]))

// ============================================================
// prep: tiled transpose W1 -> fp16 g_W[e][k]; reset lookback flags
// ============================================================
__global__ __launch_bounds__(1024)
void prep_w_kernel(const float* __restrict__ W) {
    __shared__ float t[32][33];
    int tx = threadIdx.x, ty = threadIdx.y;
    int kx = blockIdx.x * 32, ey = blockIdx.y * 32;
    t[ty][tx] = W[(size_t)(kx + ty) * DDIM + ey + tx];

    int lin = (blockIdx.y * 16 + blockIdx.x) * 1024 + ty * 32 + tx;
    if (lin < 8 * NCHUNK) g_flag[lin] = 0;

    __syncthreads();
    g_W[(size_t)(ey + ty) * DDIM + kx + tx] = __float2half_rn(t[tx][ty]);
}

// ============================================================
// mma.sync GEMM (single fp16 term) + tanh + w2-dot
//   grid (2, 512) nh-fast, block 256, 2 CTA/SM, 4-stage pipeline
// ============================================================
__global__ __launch_bounds__(256, 2)
void gemm_score_mma(const float* __restrict__ X, const float* __restrict__ b1,
                    const float* __restrict__ w2) {
    extern __shared__ __align__(128) char sm[];
    const uint32_t sbase = smem_u32(sm);
    __shared__ float s_red[4][64];

    const int tid = threadIdx.x;
    const int lane = tid & 31;
    const int warp = tid >> 5;
    const int wy = warp & 1;
    const int wx = warp >> 1;
    const int m0 = blockIdx.y * BM;
    const int n0 = blockIdx.x * BN;

    uint32_t aoff[2], boff[8];
#pragma unroll
    for (int mt = 0; mt < 2; ++mt)
        aoff[mt] = ((uint32_t)(wy * 32 + mt * 16 + (lane & 15)) * 40 + (uint32_t)(lane >> 4) * 8) * 2;
#pragma unroll
    for (int nt = 0; nt < 8; ++nt)
        boff[nt] = ((uint32_t)(wx * 64 + nt * 8 + (lane & 7)) * 40 + (uint32_t)((lane >> 3) & 1) * 8) * 2;

    float d[2][8][4];
#pragma unroll
    for (int mt = 0; mt < 2; ++mt)
#pragma unroll
        for (int nt = 0; nt < 8; ++nt)
#pragma unroll
            for (int j = 0; j < 4; ++j) d[mt][nt][j] = 0.f;

    auto loadB = [&](int kt, int sp) {
#pragma unroll
        for (int i = 0; i < 4; ++i) {
            int q = tid + i * 256;
            int row = q >> 2;
            int ch = q & 3;
            const __half* g = g_W + (size_t)(n0 + row) * DDIM + kt * BK + ch * 8;
            uint32_t sa = sbase + sp * STAGE + B_OFF + (uint32_t)row * 80 + (uint32_t)ch * 16;
            CP_ASYNC16(sa, g);
        }
        CP_COMMIT();
    };
    auto ldgA = [&](int kt, float4* rv) {
#pragma unroll
        for (int i = 0; i < 2; ++i) {
            int q = tid + i * 256;
            int row = q >> 3;
            int kf = (q & 7) << 2;
            rv[i] = *reinterpret_cast<const float4*>(
                &X[(size_t)(m0 + row) * DDIM + kt * BK + kf]);
        }
    };
    auto stsA = [&](int sp, const float4* rv) {
#pragma unroll
        for (int i = 0; i < 2; ++i) {
            int q = tid + i * 256;
            int row = q >> 3;
            int kf = (q & 7) << 2;
            float4 v = rv[i];
            uint2 hw;
            hw.x = (uint32_t)__half_as_ushort(__float2half_rn(v.x)) |
                   ((uint32_t)__half_as_ushort(__float2half_rn(v.y)) << 16);
            hw.y = (uint32_t)__half_as_ushort(__float2half_rn(v.z)) |
                   ((uint32_t)__half_as_ushort(__float2half_rn(v.w)) << 16);
            uint32_t off = (uint32_t)row * 80 + (uint32_t)kf * 2;
            *reinterpret_cast<uint2*>(sm + sp * STAGE + A_OFF + off) = hw;
        }
    };

    {
        float4 rv[2];
        loadB(0, 0); ldgA(0, rv); stsA(0, rv);
        loadB(1, 1); ldgA(1, rv); stsA(1, rv);
        loadB(2, 2); ldgA(2, rv); stsA(2, rv);
    }
    CP_WAIT2();
    __syncthreads();

    int sp = 0, spn = 3;
    for (int kt = 0; kt < KSTAGES; ++kt) {
        float4 rv[2];
        const bool pre = (kt + 3 < KSTAGES);
        if (pre) {
            loadB(kt + 3, spn);
            ldgA(kt + 3, rv);
        }

        const uint32_t bufa = sbase + sp * STAGE;
#pragma unroll
        for (int k0 = 0; k0 < 2; ++k0) {
            const uint32_t kb = (uint32_t)k0 * 32;
            uint32_t aa[2][4];
#pragma unroll
            for (int mt = 0; mt < 2; ++mt)
                LDM_X4(aa[mt], bufa + A_OFF + aoff[mt] + kb);
#pragma unroll
            for (int nt = 0; nt < 8; ++nt) {
                uint32_t bb[2];
                LDM_X2(bb, bufa + B_OFF + boff[nt] + kb);
                MMA_F16(d[0][nt], aa[0], bb);
                MMA_F16(d[1][nt], aa[1], bb);
            }
        }

        if (pre) stsA(spn, rv);
        if (kt + 1 < KSTAGES) {
            if (kt + 3 < KSTAGES) CP_WAIT2();
            else if (kt + 2 < KSTAGES) CP_WAIT1();
            else CP_WAIT0();
            __syncthreads();
        }
        sp = (sp == NSTAGE - 1) ? 0 : sp + 1;
        spn = (spn == NSTAGE - 1) ? 0 : spn + 1;
    }

    float sums[2][2];
    sums[0][0] = sums[0][1] = sums[1][0] = sums[1][1] = 0.f;
#pragma unroll
    for (int nt = 0; nt < 8; ++nt) {
        int c0 = n0 + wx * 64 + nt * 8 + (lane & 3) * 2;
        float w20 = __ldg(&w2[c0]), w21 = __ldg(&w2[c0 + 1]);
        float b10 = __ldg(&b1[c0]), b11 = __ldg(&b1[c0 + 1]);
#pragma unroll
        for (int mt = 0; mt < 2; ++mt) {
            sums[mt][0] += w20 * tanhf(d[mt][nt][0] + b10) + w21 * tanhf(d[mt][nt][1] + b11);
            sums[mt][1] += w20 * tanhf(d[mt][nt][2] + b10) + w21 * tanhf(d[mt][nt][3] + b11);
        }
    }
#pragma unroll
    for (int off = 1; off <= 2; off <<= 1) {
#pragma unroll
        for (int mt = 0; mt < 2; ++mt) {
            sums[mt][0] += __shfl_xor_sync(0xffffffffu, sums[mt][0], off);
            sums[mt][1] += __shfl_xor_sync(0xffffffffu, sums[mt][1], off);
        }
    }
    if ((lane & 3) == 0) {
        int rq = lane >> 2;
#pragma unroll
        for (int mt = 0; mt < 2; ++mt) {
            s_red[wx][wy * 32 + mt * 16 + 0 + rq] = sums[mt][0];
            s_red[wx][wy * 32 + mt * 16 + 8 + rq] = sums[mt][1];
        }
    }
    __syncthreads();
    if (tid < 64) {
        g_P[blockIdx.x][m0 + tid] =
            (s_red[0][tid] + s_red[1][tid]) + (s_red[2][tid] + s_red[3][tid]);
    }
}

// ============================================================
// fused scan: smem-cached X chunk + decoupled lookback
//   grid (64, 8), block 512, dyn smem = 128 KB (1 CTA/SM)
// ============================================================
__global__ __launch_bounds__(512)
void scan_kernel(const float* __restrict__ X, float* __restrict__ O) {
    extern __shared__ __align__(128) float Xs[];   // [CHUNK][DDIM]
    __shared__ float es[CHUNK];
    __shared__ float invd[CHUNK];
    __shared__ float sred[64];
    __shared__ float den_base, wtot0;

    const int b = blockIdx.y, ch = blockIdx.x, tid = threadIdx.x;
    const int t0 = ch * CHUNK;
    const int cid = b * NCHUNK + ch;
    const int lane = tid & 31;
    const uint32_t xs_base = smem_u32(Xs);

    // ---- cp.async: X chunk (64 x 512 fp32 = 128 KB) ----
    const float* xg = X + ((size_t)(b * 4096 + t0)) * DDIM;
#pragma unroll
    for (int i = 0; i < 16; ++i) {
        int idx = tid + i * 512;            // float4 index 0..8191
        CP_ASYNC16(xs_base + (uint32_t)idx * 16, xg + (size_t)idx * 4);
    }
    CP_COMMIT();

    // ---- es = exp(s) ----
    float e = 0.f;
    if (tid < CHUNK) {
        int m = b * 4096 + t0 + tid;
        e = expf(g_P[0][m] + g_P[1][m]);   // no shift: |s| <= ~26
        es[tid] = e;
    }
    __syncthreads();

    // ---- 2-warp inclusive scan of es ----
    float sc = e;
    if (tid < 64) {
#pragma unroll
        for (int off = 1; off < 32; off <<= 1) {
            float t = __shfl_up_sync(0xffffffffu, sc, off);
            if (lane >= off) sc += t;
        }
        if (tid == 31) wtot0 = sc;
    }
    CP_WAIT0();
    __syncthreads();   // X in smem; wtot0 visible

    if (tid == 63) g_CD[cid] = wtot0 + sc;   // chunk den total

    // ---- chunk num sum: thread d over 64 t (from smem) ----
    {
        float n0 = 0.f, n1 = 0.f;
#pragma unroll 8
        for (int t = 0; t < CHUNK; t += 2) {
            n0 = fmaf(es[t],     Xs[t * DDIM + tid],       n0);
            n1 = fmaf(es[t + 1], Xs[(t + 1) * DDIM + tid], n1);
        }
        g_CN[(size_t)cid * DDIM + tid] = n0 + n1;
    }

    // ---- publish ----
    __threadfence();
    __syncthreads();
    if (tid == 0) ((volatile int*)g_flag)[cid] = 1;

    // ---- lookback: wait for same-batch predecessors ----
    if (tid < ch) {
        while (((volatile int*)g_flag)[b * NCHUNK + tid] == 0) {}
    }
    __syncthreads();
    __threadfence();

    // den base
    if (tid < 64) sred[tid] = (tid < ch) ? g_CD[b * NCHUNK + tid] : 0.f;
    // num base (L2-hot CN reads)
    float acc = 0.f;
    {
        const float* cn = g_CN + ((size_t)(b * NCHUNK)) * DDIM + tid;
#pragma unroll 4
        for (int c = 0; c < ch; ++c) acc += cn[(size_t)c * DDIM];
    }
    __syncthreads();
    if (tid < 32) {
        float v = sred[tid] + sred[tid + 32];
#pragma unroll
        for (int off = 16; off > 0; off >>= 1)
            v += __shfl_xor_sync(0xffffffffu, v, off);
        if (tid == 0) den_base = v;
    }
    __syncthreads();
    if (tid < 64)
        invd[tid] = 1.0f / (den_base + ((tid >= 32) ? wtot0 : 0.f) + sc);
    __syncthreads();

    // ---- phase 2: inner scan from smem, write O ----
    float* op = O + ((size_t)(b * 4096 + t0)) * DDIM + tid;
#pragma unroll 8
    for (int t = 0; t < CHUNK; ++t) {
        acc = fmaf(es[t], Xs[t * DDIM + tid], acc);
        op[(size_t)t * DDIM] = acc * invd[t];
    }
}

// ============================================================
extern "C" void kernel_launch(void* const* d_in, const int* in_sizes, int n_in,
                              void* d_out, int out_size) {
    (void)in_sizes; (void)n_in; (void)out_size;
    const float* x  = (const float*)d_in[0];
    const float* W1 = (const float*)d_in[1];
    const float* b1 = (const float*)d_in[2];
    const float* w2 = (const float*)d_in[3];
    // d_in[4] = b2 : softmax shift-invariant, unused.
    float* out = (float*)d_out;

    cudaFuncSetAttribute(gemm_score_mma, cudaFuncAttributeMaxDynamicSharedMemorySize, DYN_SMEM);
    cudaFuncSetAttribute(scan_kernel, cudaFuncAttributeMaxDynamicSharedMemorySize, SCAN_SMEM);

    prep_w_kernel<<<dim3(16, 16), dim3(32, 32)>>>(W1);
    gemm_score_mma<<<dim3(2, MTOT / BM), 256, DYN_SMEM>>>(x, b1, w2);
    scan_kernel<<<dim3(NCHUNK, 8), 512, SCAN_SMEM>>>(x, out);
}

// round 14
// speedup vs baseline: 1.1847x; 1.1847x over previous
#include <cuda_runtime.h>
#include <cuda_fp16.h>
#include <math.h>
#include <stdint.h>

// Problem constants
#define MTOT 32768      // B*T
#define DDIM 512
#define NCHUNK 64       // 4096/64
#define CHUNK 64

// GEMM tiling (BM=64, 256 thr, 2 CTA/SM, 4-stage)
#define BM 64
#define BN 256
#define BK 32
#define KSTAGES 16      // 512/32

// smem stage layout (bytes), rows padded to 40 fp16 (80B) => conflict-free ldmatrix
#define A_OFF 0
#define B_OFF 5120
#define STAGE 25600
#define NSTAGE 4
#define DYN_SMEM (NSTAGE * STAGE)

// ---------------- device scratch ----------------
__device__ __half g_W[DDIM * DDIM];            // W^T fp16  [e][k]
__device__ float g_P[2][MTOT];                  // per-N-half partial scores
__device__ float g_E[MTOT];                     // exp(s)
__device__ float g_CD[8 * NCHUNK];              // per-chunk den sums
__device__ float g_CN[8 * NCHUNK * DDIM];       // per-chunk num sums

// ---------------- PTX helpers ----------------
__device__ __forceinline__ uint32_t smem_u32(const void* p) {
    uint32_t a;
    asm("{ .reg .u64 t; cvta.to.shared.u64 t, %1; cvt.u32.u64 %0, t; }" : "=r"(a) : "l"(p));
    return a;
}
#define CP_ASYNC16(sa, ga) \
    asm volatile("cp.async.cg.shared.global [%0], [%1], 16;" :: "r"(sa), "l"(ga) : "memory")
#define CP_COMMIT() asm volatile("cp.async.commit_group;" ::: "memory")
#define CP_WAIT0()  asm volatile("cp.async.wait_group 0;" ::: "memory")
#define CP_WAIT1()  asm volatile("cp.async.wait_group 1;" ::: "memory")
#define CP_WAIT2()  asm volatile("cp.async.wait_group 2;" ::: "memory")

#define LDM_X4(r, addr) \
    asm volatile("ldmatrix.sync.aligned.m8n8.x4.shared.b16 {%0,%1,%2,%3}, [%4];" \
        : "=r"((r)[0]), "=r"((r)[1]), "=r"((r)[2]), "=r"((r)[3]) : "r"(addr))

#define MMA_F16(d, a, b0, b1) \
    asm volatile("mma.sync.aligned.m16n8k16.row.col.f32.f16.f16.f32 " \
        "{%0,%1,%2,%3}, {%4,%5,%6,%7}, {%8,%9}, {%0,%1,%2,%3};" \
        : "+f"((d)[0]), "+f"((d)[1]), "+f"((d)[2]), "+f"((d)[3]) \
        : "r"((a)[0]), "r"((a)[1]), "r"((a)[2]), "r"((a)[3]), "r"(b0), "r"(b1))

// ============================================================
// prep: tiled transpose W1 -> fp16 g_W[e][k]
// ============================================================
__global__ __launch_bounds__(1024)
void prep_w_kernel(const float* __restrict__ W) {
    __shared__ float t[32][33];
    int tx = threadIdx.x, ty = threadIdx.y;
    int kx = blockIdx.x * 32, ey = blockIdx.y * 32;
    t[ty][tx] = W[(size_t)(kx + ty) * DDIM + ey + tx];
    __syncthreads();
    g_W[(size_t)(ey + ty) * DDIM + kx + tx] = __float2half_rn(t[tx][ty]);
}

// ============================================================
// mma.sync GEMM (single fp16 term) + tanh + w2-dot
//   grid (2, 512) nh-fast, block 256, 2 CTA/SM, 4-stage pipeline
//   B fragments loaded pairwise via ldmatrix.x4 (2 nt tiles per op)
// ============================================================
__global__ __launch_bounds__(256, 2)
void gemm_score_mma(const float* __restrict__ X, const float* __restrict__ b1,
                    const float* __restrict__ w2) {
    extern __shared__ __align__(128) char sm[];
    const uint32_t sbase = smem_u32(sm);
    __shared__ float s_red[4][64];

    const int tid = threadIdx.x;
    const int lane = tid & 31;
    const int warp = tid >> 5;
    const int wy = warp & 1;
    const int wx = warp >> 1;
    const int m0 = blockIdx.y * BM;
    const int n0 = blockIdx.x * BN;

    uint32_t aoff[2], boff4[4];
#pragma unroll
    for (int mt = 0; mt < 2; ++mt)
        aoff[mt] = ((uint32_t)(wy * 32 + mt * 16 + (lane & 15)) * 40 + (uint32_t)(lane >> 4) * 8) * 2;
    // x4 B: matrices m0,m1 = nt=2p k-halves; m2,m3 = nt=2p+1 k-halves
#pragma unroll
    for (int p = 0; p < 4; ++p)
        boff4[p] = (uint32_t)(wx * 64 + (2 * p + (lane >> 4)) * 8 + (lane & 7)) * 80 +
                   (uint32_t)((lane >> 3) & 1) * 16;

    float d[2][8][4];
#pragma unroll
    for (int mt = 0; mt < 2; ++mt)
#pragma unroll
        for (int nt = 0; nt < 8; ++nt)
#pragma unroll
            for (int j = 0; j < 4; ++j) d[mt][nt][j] = 0.f;

    auto loadB = [&](int kt, int sp) {
#pragma unroll
        for (int i = 0; i < 4; ++i) {
            int q = tid + i * 256;
            int row = q >> 2;
            int ch = q & 3;
            const __half* g = g_W + (size_t)(n0 + row) * DDIM + kt * BK + ch * 8;
            uint32_t sa = sbase + sp * STAGE + B_OFF + (uint32_t)row * 80 + (uint32_t)ch * 16;
            CP_ASYNC16(sa, g);
        }
        CP_COMMIT();
    };
    auto ldgA = [&](int kt, float4* rv) {
#pragma unroll
        for (int i = 0; i < 2; ++i) {
            int q = tid + i * 256;
            int row = q >> 3;
            int kf = (q & 7) << 2;
            rv[i] = *reinterpret_cast<const float4*>(
                &X[(size_t)(m0 + row) * DDIM + kt * BK + kf]);
        }
    };
    auto stsA = [&](int sp, const float4* rv) {
#pragma unroll
        for (int i = 0; i < 2; ++i) {
            int q = tid + i * 256;
            int row = q >> 3;
            int kf = (q & 7) << 2;
            float4 v = rv[i];
            uint2 hw;
            hw.x = (uint32_t)__half_as_ushort(__float2half_rn(v.x)) |
                   ((uint32_t)__half_as_ushort(__float2half_rn(v.y)) << 16);
            hw.y = (uint32_t)__half_as_ushort(__float2half_rn(v.z)) |
                   ((uint32_t)__half_as_ushort(__float2half_rn(v.w)) << 16);
            uint32_t off = (uint32_t)row * 80 + (uint32_t)kf * 2;
            *reinterpret_cast<uint2*>(sm + sp * STAGE + A_OFF + off) = hw;
        }
    };

    // ---- prologue: stages 0,1,2 ----
    {
        float4 rv[2];
        loadB(0, 0); ldgA(0, rv); stsA(0, rv);
        loadB(1, 1); ldgA(1, rv); stsA(1, rv);
        loadB(2, 2); ldgA(2, rv); stsA(2, rv);
    }
    CP_WAIT2();
    __syncthreads();

    // ---- main loop ----
    int sp = 0, spn = 3;
    for (int kt = 0; kt < KSTAGES; ++kt) {
        float4 rv[2];
        const bool pre = (kt + 3 < KSTAGES);
        if (pre) {
            loadB(kt + 3, spn);
            ldgA(kt + 3, rv);
        }

        const uint32_t bufa = sbase + sp * STAGE;
#pragma unroll
        for (int k0 = 0; k0 < 2; ++k0) {
            const uint32_t kb = (uint32_t)k0 * 32;
            uint32_t aa[2][4];
#pragma unroll
            for (int mt = 0; mt < 2; ++mt)
                LDM_X4(aa[mt], bufa + A_OFF + aoff[mt] + kb);
#pragma unroll
            for (int p = 0; p < 4; ++p) {
                uint32_t bb[4];
                LDM_X4(bb, bufa + B_OFF + boff4[p] + kb);
                MMA_F16(d[0][2 * p],     aa[0], bb[0], bb[1]);
                MMA_F16(d[1][2 * p],     aa[1], bb[0], bb[1]);
                MMA_F16(d[0][2 * p + 1], aa[0], bb[2], bb[3]);
                MMA_F16(d[1][2 * p + 1], aa[1], bb[2], bb[3]);
            }
        }

        if (pre) stsA(spn, rv);
        if (kt + 1 < KSTAGES) {
            if (kt + 3 < KSTAGES) CP_WAIT2();
            else if (kt + 2 < KSTAGES) CP_WAIT1();
            else CP_WAIT0();
            __syncthreads();
        }
        sp = (sp == NSTAGE - 1) ? 0 : sp + 1;
        spn = (spn == NSTAGE - 1) ? 0 : spn + 1;
    }

    // ---- epilogue: tanh + w2 dot, reduce ----
    float sums[2][2];
    sums[0][0] = sums[0][1] = sums[1][0] = sums[1][1] = 0.f;
#pragma unroll
    for (int nt = 0; nt < 8; ++nt) {
        int c0 = n0 + wx * 64 + nt * 8 + (lane & 3) * 2;
        float w20 = __ldg(&w2[c0]), w21 = __ldg(&w2[c0 + 1]);
        float b10 = __ldg(&b1[c0]), b11 = __ldg(&b1[c0 + 1]);
#pragma unroll
        for (int mt = 0; mt < 2; ++mt) {
            sums[mt][0] += w20 * tanhf(d[mt][nt][0] + b10) + w21 * tanhf(d[mt][nt][1] + b11);
            sums[mt][1] += w20 * tanhf(d[mt][nt][2] + b10) + w21 * tanhf(d[mt][nt][3] + b11);
        }
    }
#pragma unroll
    for (int off = 1; off <= 2; off <<= 1) {
#pragma unroll
        for (int mt = 0; mt < 2; ++mt) {
            sums[mt][0] += __shfl_xor_sync(0xffffffffu, sums[mt][0], off);
            sums[mt][1] += __shfl_xor_sync(0xffffffffu, sums[mt][1], off);
        }
    }
    if ((lane & 3) == 0) {
        int rq = lane >> 2;
#pragma unroll
        for (int mt = 0; mt < 2; ++mt) {
            s_red[wx][wy * 32 + mt * 16 + 0 + rq] = sums[mt][0];
            s_red[wx][wy * 32 + mt * 16 + 8 + rq] = sums[mt][1];
        }
    }
    __syncthreads();
    if (tid < 64) {
        g_P[blockIdx.x][m0 + tid] =
            (s_red[0][tid] + s_red[1][tid]) + (s_red[2][tid] + s_red[3][tid]);
    }
}

// ============================================================
// chunk sums (fused exp, float4, 4-way t-split): grid (64, 8), block 512
// ============================================================
__global__ __launch_bounds__(512)
void chunk_kernel(const float* __restrict__ X) {
    int b = blockIdx.y, ch = blockIdx.x, tid = threadIdx.x;
    int t0 = ch * CHUNK;
    __shared__ float es[CHUNK];
    __shared__ float4 red[512];
    if (tid < CHUNK) {
        int m = b * 4096 + t0 + tid;
        float ev = expf(g_P[0][m] + g_P[1][m]);   // no shift: |s| <= ~26
        es[tid] = ev;
        g_E[m] = ev;
    }
    __syncthreads();
    if (tid < 32) {
        float s4 = es[tid] + es[tid + 32];
#pragma unroll
        for (int off = 16; off > 0; off >>= 1)
            s4 += __shfl_xor_sync(0xffffffffu, s4, off);
        if (tid == 0) g_CD[b * NCHUNK + ch] = s4;
    }
    int q = tid >> 7, dt = tid & 127;
    const float4* xp = (const float4*)(X + ((size_t)(b * 4096 + t0 + q * 16)) * DDIM) + dt;
    float4 acc = make_float4(0.f, 0.f, 0.f, 0.f);
#pragma unroll 4
    for (int t = 0; t < 16; ++t) {
        float e = es[q * 16 + t];
        float4 v = xp[(size_t)t * 128];
        acc.x = fmaf(e, v.x, acc.x); acc.y = fmaf(e, v.y, acc.y);
        acc.z = fmaf(e, v.z, acc.z); acc.w = fmaf(e, v.w, acc.w);
    }
    red[tid] = acc;
    __syncthreads();
    if (tid < 128) {
        float4 a = red[tid], b4 = red[tid + 128], c = red[tid + 256], dd = red[tid + 384];
        float4 o = make_float4((a.x + b4.x) + (c.x + dd.x), (a.y + b4.y) + (c.y + dd.y),
                               (a.z + b4.z) + (c.z + dd.z), (a.w + b4.w) + (c.w + dd.w));
        ((float4*)(g_CN + ((size_t)(b * NCHUNK + ch)) * DDIM))[tid] = o;
    }
}

// ============================================================
// final: chunk prefix + parallel es-scan + scalar inner scan
//   grid (64, 8), block 512; O written with streaming hint (.cs)
// ============================================================
__global__ __launch_bounds__(512)
void final_kernel(const float* __restrict__ X, float* __restrict__ O) {
    int b = blockIdx.y, ch = blockIdx.x, tid = threadIdx.x;
    int t0 = ch * CHUNK;
    const int lane = tid & 31;
    __shared__ float es[CHUNK];
    __shared__ float invd[CHUNK];
    __shared__ float sred[64];
    __shared__ float den_base, wtot0;

    float e = 0.f;
    if (tid < 64) {
        e = g_E[b * 4096 + t0 + tid];
        es[tid] = e;
        sred[tid] = (tid < ch) ? g_CD[b * NCHUNK + tid] : 0.f;
    }
    __syncthreads();

    if (tid < 32) {
        float v = sred[tid] + sred[tid + 32];
#pragma unroll
        for (int off = 16; off > 0; off >>= 1)
            v += __shfl_xor_sync(0xffffffffu, v, off);
        if (tid == 0) den_base = v;
    }
    float sc = e;
    if (tid < 64) {
#pragma unroll
        for (int off = 1; off < 32; off <<= 1) {
            float t = __shfl_up_sync(0xffffffffu, sc, off);
            if (lane >= off) sc += t;
        }
        if (tid == 31) wtot0 = sc;
    }

    float acc = 0.f;
    {
        const float* cn = g_CN + ((size_t)(b * NCHUNK)) * DDIM + tid;
#pragma unroll 4
        for (int c = 0; c < ch; ++c) acc += cn[(size_t)c * DDIM];
    }
    __syncthreads();
    if (tid < 64)
        invd[tid] = 1.0f / (den_base + ((tid >= 32) ? wtot0 : 0.f) + sc);
    __syncthreads();

    const float* xp = X + ((size_t)(b * 4096 + t0)) * DDIM + tid;
    float* op = O + ((size_t)(b * 4096 + t0)) * DDIM + tid;
#pragma unroll 8
    for (int t = 0; t < CHUNK; ++t) {
        acc = fmaf(es[t], xp[(size_t)t * DDIM], acc);
        __stcs(op + (size_t)t * DDIM, acc * invd[t]);   // streaming: keep X in L2
    }
}

// ============================================================
extern "C" void kernel_launch(void* const* d_in, const int* in_sizes, int n_in,
                              void* d_out, int out_size) {
    (void)in_sizes; (void)n_in; (void)out_size;
    const float* x  = (const float*)d_in[0];
    const float* W1 = (const float*)d_in[1];
    const float* b1 = (const float*)d_in[2];
    const float* w2 = (const float*)d_in[3];
    // d_in[4] = b2 : softmax shift-invariant, unused.
    float* out = (float*)d_out;

    cudaFuncSetAttribute(gemm_score_mma, cudaFuncAttributeMaxDynamicSharedMemorySize, DYN_SMEM);

    prep_w_kernel<<<dim3(16, 16), dim3(32, 32)>>>(W1);
    gemm_score_mma<<<dim3(2, MTOT / BM), 256, DYN_SMEM>>>(x, b1, w2);
    dim3 g2(NCHUNK, 8);
    chunk_kernel<<<g2, 512>>>(x);
    final_kernel<<<g2, 512>>>(x, out);
}